// round 8
// baseline (speedup 1.0000x reference)
#include <cuda_runtime.h>
#include <math.h>
#include <stdint.h>

#define BB   2
#define SS   2048
#define DD   512
#define HH   8
#define DKK  64
#define BHH  (BB*HH)

// ---------------- scratch (device globals; no allocation allowed) ----------
__device__ float g_qh[BHH*SS*DKK];          // [bh][s][dk] tf32 bits, pre-scaled 1/8
__device__ float g_kh[BHH*SS*DKK];          // tf32 bits
__device__ float g_vt[BHH*DKK*SS];          // V^T [bh][dk][s], tf32 bits
__device__ float g_at[BB*SS*DD];            // attention out [b][s][h*64+dk]
__device__ float g_cos[SS*DKK];
__device__ float g_sin[SS*DKK];
__device__ float g_sc[67108864];            // scores -> unnormalized P (tf32 bits)

// ---------------- helpers ----------------------------------------------------
__device__ __forceinline__ uint32_t f2tf(float f)
{
    uint32_t u;
    asm("cvt.rna.tf32.f32 %0, %1;" : "=r"(u) : "f"(f));
    return u;
}

__device__ __forceinline__ void mma8(float* c, const uint32_t* a, const uint32_t* b)
{
    asm volatile(
        "mma.sync.aligned.m16n8k8.row.col.f32.tf32.tf32.f32 "
        "{%0,%1,%2,%3}, {%4,%5,%6,%7}, {%8,%9}, {%0,%1,%2,%3};\n"
        : "+f"(c[0]), "+f"(c[1]), "+f"(c[2]), "+f"(c[3])
        : "r"(a[0]), "r"(a[1]), "r"(a[2]), "r"(a[3]), "r"(b[0]), "r"(b[1]));
}

#define GEMM_SMEM_BYTES (4*128*36*4)   // 73728: A0,A1,B0,B1

// ---------------- RoPE table ------------------------------------------------
__global__ void rope_tab_kernel()
{
    int idx = blockIdx.x * blockDim.x + threadIdx.x;
    if (idx >= SS * 32) return;
    int s = idx >> 5;
    int m = idx & 31;
    float f = (float)s * powf(10000.f, -(float)(2 * m) / 64.f);
    float sn, cs;
    sincosf(f, &sn, &cs);
    g_cos[s*64 + 2*m]     = cs;
    g_cos[s*64 + 2*m + 1] = cs;
    g_sin[s*64 + 2*m]     = sn;
    g_sin[s*64 + 2*m + 1] = sn;
}

// ---------------- fused QKV projection + RoPE (tf32 mma, double-buffered) ----
__global__ __launch_bounds__(256) void proj_kernel(
    const float* __restrict__ qx, const float* __restrict__ kx, const float* __restrict__ vx,
    const float* __restrict__ Wq, const float* __restrict__ bq,
    const float* __restrict__ Wk, const float* __restrict__ bk,
    const float* __restrict__ Wv, const float* __restrict__ bv)
{
    extern __shared__ uint32_t dyn[];
    uint32_t* Abuf[2] = { dyn,              dyn + 128*36 };
    uint32_t* Bbuf[2] = { dyn + 2*128*36,   dyn + 3*128*36 };

    int which = blockIdx.z;
    const float* X    = (which == 0) ? qx : (which == 1) ? kx : vx;
    const float* W    = (which == 0) ? Wq : (which == 1) ? Wk : Wv;
    const float* bias = (which == 0) ? bq : (which == 1) ? bk : bv;

    int tid  = threadIdx.x;
    int wid  = tid >> 5, lane = tid & 31;
    int g    = lane >> 2, t = lane & 3;
    int wm   = wid >> 2, wn = wid & 3;
    int n0   = blockIdx.x * 128;
    int m0   = blockIdx.y * 128;

    float c[4][4][4];
    #pragma unroll
    for (int mf = 0; mf < 4; mf++)
        #pragma unroll
        for (int nf = 0; nf < 4; nf++)
            #pragma unroll
            for (int u = 0; u < 4; u++) c[mf][nf][u] = 0.f;

    int lr = tid >> 1;
    int lc = (tid & 1) * 16;
    const float* Xrow = X + (size_t)(m0 + lr) * 512 + lc;
    const float* Wrow = W + (size_t)(n0 + lr) * 512 + lc;

    float4 xa[4], wb[4];
    #pragma unroll
    for (int u = 0; u < 4; u++) {
        xa[u] = *(const float4*)(Xrow + u*4);
        wb[u] = *(const float4*)(Wrow + u*4);
    }
    {
        uint32_t* Ad = Abuf[0] + lr*36 + lc;
        uint32_t* Bd = Bbuf[0] + lr*36 + lc;
        #pragma unroll
        for (int u = 0; u < 4; u++) {
            Ad[u*4+0] = f2tf(xa[u].x); Ad[u*4+1] = f2tf(xa[u].y);
            Ad[u*4+2] = f2tf(xa[u].z); Ad[u*4+3] = f2tf(xa[u].w);
            Bd[u*4+0] = f2tf(wb[u].x); Bd[u*4+1] = f2tf(wb[u].y);
            Bd[u*4+2] = f2tf(wb[u].z); Bd[u*4+3] = f2tf(wb[u].w);
        }
    }
    __syncthreads();

    for (int it = 0; it < 16; it++) {
        int cur = it & 1;
        int kn  = (it + 1) * 32;
        if (kn < 512) {
            #pragma unroll
            for (int u = 0; u < 4; u++) {
                xa[u] = *(const float4*)(Xrow + kn + u*4);
                wb[u] = *(const float4*)(Wrow + kn + u*4);
            }
        }
        const uint32_t* Ac = Abuf[cur];
        const uint32_t* Bc = Bbuf[cur];
        #pragma unroll
        for (int k8 = 0; k8 < 32; k8 += 8) {
            uint32_t a[4][4], b[4][2];
            #pragma unroll
            for (int mf = 0; mf < 4; mf++) {
                int r = wm*64 + mf*16 + g;
                a[mf][0] = Ac[r*36 + k8+t];       a[mf][1] = Ac[(r+8)*36 + k8+t];
                a[mf][2] = Ac[r*36 + k8+t+4];     a[mf][3] = Ac[(r+8)*36 + k8+t+4];
            }
            #pragma unroll
            for (int nf = 0; nf < 4; nf++) {
                int rn = wn*32 + nf*8 + g;
                b[nf][0] = Bc[rn*36 + k8+t];      b[nf][1] = Bc[rn*36 + k8+t+4];
            }
            #pragma unroll
            for (int mf = 0; mf < 4; mf++)
                #pragma unroll
                for (int nf = 0; nf < 4; nf++)
                    mma8(c[mf][nf], a[mf], b[nf]);
        }
        if (kn < 512) {
            uint32_t* Ad = Abuf[cur ^ 1] + lr*36 + lc;
            uint32_t* Bd = Bbuf[cur ^ 1] + lr*36 + lc;
            #pragma unroll
            for (int u = 0; u < 4; u++) {
                Ad[u*4+0] = f2tf(xa[u].x); Ad[u*4+1] = f2tf(xa[u].y);
                Ad[u*4+2] = f2tf(xa[u].z); Ad[u*4+3] = f2tf(xa[u].w);
                Bd[u*4+0] = f2tf(wb[u].x); Bd[u*4+1] = f2tf(wb[u].y);
                Bd[u*4+2] = f2tf(wb[u].z); Bd[u*4+3] = f2tf(wb[u].w);
            }
            __syncthreads();
        }
    }

    // ---- epilogue: bias (+ RoPE for q/k); store tf32-rounded bits ----
    #pragma unroll
    for (int nf = 0; nf < 4; nf++) {
        int col = n0 + wn*32 + nf*8 + t*2;
        int hh  = col >> 6, dk = col & 63;
        float bce = bias[col], bco = bias[col+1];
        #pragma unroll
        for (int mf = 0; mf < 4; mf++) {
            #pragma unroll
            for (int half = 0; half < 2; half++) {
                int row  = m0 + wm*64 + mf*16 + g + half*8;
                int srow = row & (SS-1);
                int bidx = row >> 11;
                float e = c[mf][nf][half*2+0] + bce;
                float o = c[mf][nf][half*2+1] + bco;
                if (which < 2) {
                    float cs = g_cos[srow*64 + dk];
                    float sn = g_sin[srow*64 + dk];
                    float sc = (which == 0) ? 0.125f : 1.0f;
                    float ne = __uint_as_float(f2tf((e*cs - o*sn) * sc));
                    float no = __uint_as_float(f2tf((o*cs + e*sn) * sc));
                    float* Y = (which == 0) ? g_qh : g_kh;
                    *(float2*)(Y + (((size_t)(bidx*HH + hh))*SS + srow)*DKK + dk)
                        = make_float2(ne, no);
                } else {
                    size_t vb = (size_t)(bidx*HH + hh) * DKK;
                    g_vt[(vb + dk    )*SS + srow] = __uint_as_float(f2tf(e));
                    g_vt[(vb + dk + 1)*SS + srow] = __uint_as_float(f2tf(o));
                }
            }
        }
    }
}

// ---------------- output projection (tf32 mma, double-buffered) ---------------
__global__ __launch_bounds__(256) void out_proj_kernel(
    const float* __restrict__ W, const float* __restrict__ bias, float* __restrict__ out)
{
    extern __shared__ uint32_t dyn[];
    uint32_t* Abuf[2] = { dyn,              dyn + 128*36 };
    uint32_t* Bbuf[2] = { dyn + 2*128*36,   dyn + 3*128*36 };

    int tid  = threadIdx.x;
    int wid  = tid >> 5, lane = tid & 31;
    int g    = lane >> 2, t = lane & 3;
    int wm   = wid >> 2, wn = wid & 3;
    int n0   = blockIdx.x * 128;
    int m0   = blockIdx.y * 128;

    float c[4][4][4];
    #pragma unroll
    for (int mf = 0; mf < 4; mf++)
        #pragma unroll
        for (int nf = 0; nf < 4; nf++)
            #pragma unroll
            for (int u = 0; u < 4; u++) c[mf][nf][u] = 0.f;

    int lr = tid >> 1;
    int lc = (tid & 1) * 16;
    const float* Xrow = g_at + (size_t)(m0 + lr) * 512 + lc;
    const float* Wrow = W    + (size_t)(n0 + lr) * 512 + lc;

    float4 xa[4], wb[4];
    #pragma unroll
    for (int u = 0; u < 4; u++) {
        xa[u] = *(const float4*)(Xrow + u*4);
        wb[u] = *(const float4*)(Wrow + u*4);
    }
    {
        uint32_t* Ad = Abuf[0] + lr*36 + lc;
        uint32_t* Bd = Bbuf[0] + lr*36 + lc;
        #pragma unroll
        for (int u = 0; u < 4; u++) {
            Ad[u*4+0] = f2tf(xa[u].x); Ad[u*4+1] = f2tf(xa[u].y);
            Ad[u*4+2] = f2tf(xa[u].z); Ad[u*4+3] = f2tf(xa[u].w);
            Bd[u*4+0] = f2tf(wb[u].x); Bd[u*4+1] = f2tf(wb[u].y);
            Bd[u*4+2] = f2tf(wb[u].z); Bd[u*4+3] = f2tf(wb[u].w);
        }
    }
    __syncthreads();

    for (int it = 0; it < 16; it++) {
        int cur = it & 1;
        int kn  = (it + 1) * 32;
        if (kn < 512) {
            #pragma unroll
            for (int u = 0; u < 4; u++) {
                xa[u] = *(const float4*)(Xrow + kn + u*4);
                wb[u] = *(const float4*)(Wrow + kn + u*4);
            }
        }
        const uint32_t* Ac = Abuf[cur];
        const uint32_t* Bc = Bbuf[cur];
        #pragma unroll
        for (int k8 = 0; k8 < 32; k8 += 8) {
            uint32_t a[4][4], b[4][2];
            #pragma unroll
            for (int mf = 0; mf < 4; mf++) {
                int r = wm*64 + mf*16 + g;
                a[mf][0] = Ac[r*36 + k8+t];       a[mf][1] = Ac[(r+8)*36 + k8+t];
                a[mf][2] = Ac[r*36 + k8+t+4];     a[mf][3] = Ac[(r+8)*36 + k8+t+4];
            }
            #pragma unroll
            for (int nf = 0; nf < 4; nf++) {
                int rn = wn*32 + nf*8 + g;
                b[nf][0] = Bc[rn*36 + k8+t];      b[nf][1] = Bc[rn*36 + k8+t+4];
            }
            #pragma unroll
            for (int mf = 0; mf < 4; mf++)
                #pragma unroll
                for (int nf = 0; nf < 4; nf++)
                    mma8(c[mf][nf], a[mf], b[nf]);
        }
        if (kn < 512) {
            uint32_t* Ad = Abuf[cur ^ 1] + lr*36 + lc;
            uint32_t* Bd = Bbuf[cur ^ 1] + lr*36 + lc;
            #pragma unroll
            for (int u = 0; u < 4; u++) {
                Ad[u*4+0] = f2tf(xa[u].x); Ad[u*4+1] = f2tf(xa[u].y);
                Ad[u*4+2] = f2tf(xa[u].z); Ad[u*4+3] = f2tf(xa[u].w);
                Bd[u*4+0] = f2tf(wb[u].x); Bd[u*4+1] = f2tf(wb[u].y);
                Bd[u*4+2] = f2tf(wb[u].z); Bd[u*4+3] = f2tf(wb[u].w);
            }
            __syncthreads();
        }
    }

    #pragma unroll
    for (int nf = 0; nf < 4; nf++) {
        int col = n0 + wn*32 + nf*8 + t*2;
        float bce = bias[col], bco = bias[col+1];
        #pragma unroll
        for (int mf = 0; mf < 4; mf++) {
            #pragma unroll
            for (int half = 0; half < 2; half++) {
                int row = m0 + wm*64 + mf*16 + g + half*8;
                *(float2*)(out + (size_t)row*512 + col)
                    = make_float2(c[mf][nf][half*2+0] + bce, c[mf][nf][half*2+1] + bco);
            }
        }
    }
}

// ---------------- causal score GEMM S = Q K^T (single-barrier, K resident) ---
__global__ __launch_bounds__(256) void score_kernel()
{
    extern __shared__ uint32_t dyn[];
    int qt = blockIdx.x, kt = blockIdx.y, bh = blockIdx.z;
    if (kt > qt) return;

    uint32_t* Qb[2] = { dyn,            dyn + 128*36 };
    uint32_t* Kb[2] = { dyn + 2*128*36, dyn + 3*128*36 };

    const uint32_t* qb = (const uint32_t*)g_qh + ((size_t)bh * SS + (size_t)qt*128) * DKK;
    const uint32_t* kb = (const uint32_t*)g_kh + ((size_t)bh * SS + (size_t)kt*128) * DKK;

    int tid  = threadIdx.x;
    int wid  = tid >> 5, lane = tid & 31;
    int g    = lane >> 2, t = lane & 3;
    int wm   = wid >> 2, wn = wid & 3;

    // fill both 32-col chunks of Q and K (8 uint4 per thread per matrix)
    #pragma unroll
    for (int u = 0; u < 8; u++) {
        int idx = tid + u*256;            // 0..2047
        int row = idx >> 4;
        int c4  = (idx & 15) << 2;        // float col 0..60 step 4
        int kc  = c4 >> 5;
        int ci  = c4 & 31;
        *(uint4*)&Qb[kc][row*36 + ci] = *(const uint4*)(qb + (size_t)row*64 + c4);
        *(uint4*)&Kb[kc][row*36 + ci] = *(const uint4*)(kb + (size_t)row*64 + c4);
    }
    __syncthreads();

    float c[4][4][4];
    #pragma unroll
    for (int mf = 0; mf < 4; mf++)
        #pragma unroll
        for (int nf = 0; nf < 4; nf++)
            #pragma unroll
            for (int u = 0; u < 4; u++) c[mf][nf][u] = 0.f;

    #pragma unroll
    for (int kc = 0; kc < 2; kc++) {
        const uint32_t* Qc = Qb[kc];
        const uint32_t* Kc = Kb[kc];
        #pragma unroll
        for (int k8 = 0; k8 < 32; k8 += 8) {
            uint32_t a[4][4], b[4][2];
            #pragma unroll
            for (int mf = 0; mf < 4; mf++) {
                int r = wm*64 + mf*16 + g;
                a[mf][0] = Qc[r*36 + k8+t];       a[mf][1] = Qc[(r+8)*36 + k8+t];
                a[mf][2] = Qc[r*36 + k8+t+4];     a[mf][3] = Qc[(r+8)*36 + k8+t+4];
            }
            #pragma unroll
            for (int nf = 0; nf < 4; nf++) {
                int rn = wn*32 + nf*8 + g;
                b[nf][0] = Kc[rn*36 + k8+t];      b[nf][1] = Kc[rn*36 + k8+t+4];
            }
            #pragma unroll
            for (int mf = 0; mf < 4; mf++)
                #pragma unroll
                for (int nf = 0; nf < 4; nf++)
                    mma8(c[mf][nf], a[mf], b[nf]);
        }
    }

    float* C = g_sc + (size_t)bh * SS * SS;
    int i0 = qt * 128, j0 = kt * 128;
    #pragma unroll
    for (int nf = 0; nf < 4; nf++) {
        int col = j0 + wn*32 + nf*8 + t*2;
        #pragma unroll
        for (int mf = 0; mf < 4; mf++) {
            #pragma unroll
            for (int half = 0; half < 2; half++) {
                int row = i0 + wm*64 + mf*16 + g + half*8;
                *(float2*)(C + (size_t)row*SS + col)
                    = make_float2(c[mf][nf][half*2+0], c[mf][nf][half*2+1]);
            }
        }
    }
}

// ---------------- per-row decay softmax (no-max, unnormalized output) --------
__global__ __launch_bounds__(256) void row_kernel(const float* __restrict__ gammas)
{
    __shared__ float swp[17];
    int rid = blockIdx.x;
    int bh  = rid >> 11;
    int i   = rid & (SS - 1);
    int h   = bh & (HH - 1);
    int tid = threadIdx.x, wid = tid >> 5, lane = tid & 31;

    float* row = g_sc + (size_t)bh * SS * SS + (size_t)i * SS;
    int lim = ((i >> 7) + 1) << 7;

    if (i == 0) {
        if (tid < 32) ((float4*)row)[tid] = make_float4(0.f, 0.f, 0.f, 0.f);
        return;
    }

    const bool act = (wid << 8) < lim;
    const int base = tid * 8;

    float sv[8];
    float epre[8];
    float run = 0.f;
    if (act) {
        float4 v0 = *(const float4*)(row + base);
        float4 v1 = *(const float4*)(row + base + 4);
        float tmp[8] = {v0.x, v0.y, v0.z, v0.w, v1.x, v1.y, v1.z, v1.w};
        #pragma unroll
        for (int u = 0; u < 8; u++) {
            sv[u] = (base + u <= i) ? tmp[u] : -3.0e38f;
            run  += __expf(sv[u]);          // masked lanes contribute exactly 0
            epre[u] = run;
        }
    }

    // --- block inclusive scan of per-thread sums (the only collective) ---
    float x = run;
    #pragma unroll
    for (int d = 1; d < 32; d <<= 1) {
        float y = __shfl_up_sync(0xffffffffu, x, d);
        if (lane >= d) x += y;
    }
    if (lane == 31) swp[wid] = x;
    __syncthreads();
    if (tid == 0) {
        float s = 0.f;
        #pragma unroll
        for (int w = 0; w < 8; w++) { float tw = swp[w]; swp[8 + w] = s; s += tw; }
        swp[16] = s;
    }
    __syncthreads();

    if (act) {
        float off = swp[8 + wid] + (x - run);
        float l1  = swp[16];
        float gam = gammas[h * SS + i];
        float sp  = (gam > 20.f) ? gam : log1pf(__expf(gam));
        float gg  = -sp;
        float inv_l1 = 1.f / l1;
        float fi  = (float)i - (float)base;

        uint32_t e2[8];
        #pragma unroll
        for (int u = 0; u < 8; u++) {
            float suffix = l1 - (off + epre[u]);
            float dsq    = suffix * inv_l1 * (fi - (float)u);
            float dist   = sqrtf(fmaxf(dsq, 0.f));
            float eff    = fmaxf(__expf(dist * gg), 1e-5f);
            e2[u] = f2tf(__expf(eff * sv[u]));    // masked -> exp(-huge) = 0
        }
        if (base < lim) {
            *(uint4*)(row + base)     = make_uint4(e2[0], e2[1], e2[2], e2[3]);
            *(uint4*)(row + base + 4) = make_uint4(e2[4], e2[5], e2[6], e2[7]);
        }
    }
}

// ---------------- causal PV GEMM O = P @ V (64-row tiles, double-buffered) ----
__global__ __launch_bounds__(256) void pv_kernel()
{
    int mt = (int)gridDim.x - 1 - (int)blockIdx.x;   // longest-k tiles first
    int bh = blockIdx.y;
    int qt = mt >> 1;
    int m0 = mt * 64;

    __shared__ uint32_t Ps[2][64][36];
    __shared__ uint32_t Vs[2][64][36];
    __shared__ float    sl2[256];

    const uint32_t* P  = (const uint32_t*)g_sc + (size_t)bh * SS * SS;
    const uint32_t* vb = (const uint32_t*)g_vt + (size_t)bh * DKK * SS;

    int tid  = threadIdx.x;
    int wid  = tid >> 5, lane = tid & 31;
    int g    = lane >> 2, t = lane & 3;
    int wm   = wid >> 1, wn = wid & 1;

    float c[4][4];
    #pragma unroll
    for (int nf = 0; nf < 4; nf++)
        #pragma unroll
        for (int u = 0; u < 4; u++) c[nf][u] = 0.f;

    int lr = tid >> 2;
    int lc = (tid & 3) * 8;
    int kmax = (qt + 1) * 128;
    const uint32_t* Prow = P + (size_t)(m0 + lr) * SS + lc;
    const uint32_t* Vrow = vb + (size_t)lr * SS + lc;

    float l2acc = 0.f;

    uint4 pv[2], vv[2];
    pv[0] = *(const uint4*)(Prow);
    pv[1] = *(const uint4*)(Prow + 4);
    vv[0] = *(const uint4*)(Vrow);
    vv[1] = *(const uint4*)(Vrow + 4);

    #pragma unroll
    for (int u = 0; u < 2; u++) {
        *(uint4*)&Ps[0][lr][lc + u*4] = pv[u];
        *(uint4*)&Vs[0][lr][lc + u*4] = vv[u];
        l2acc += __uint_as_float(pv[u].x) + __uint_as_float(pv[u].y)
               + __uint_as_float(pv[u].z) + __uint_as_float(pv[u].w);
    }
    __syncthreads();

    int nit = kmax >> 5;
    for (int it = 0; it < nit; it++) {
        int cur = it & 1;
        int kn  = (it + 1) * 32;
        if (kn < kmax) {
            pv[0] = *(const uint4*)(Prow + kn);
            pv[1] = *(const uint4*)(Prow + kn + 4);
            vv[0] = *(const uint4*)(Vrow + kn);
            vv[1] = *(const uint4*)(Vrow + kn + 4);
        }
        #pragma unroll
        for (int k8 = 0; k8 < 32; k8 += 8) {
            uint32_t a[4], b[4][2];
            int r = wm*16 + g;
            a[0] = Ps[cur][r][k8+t];     a[1] = Ps[cur][r+8][k8+t];
            a[2] = Ps[cur][r][k8+t+4];   a[3] = Ps[cur][r+8][k8+t+4];
            #pragma unroll
            for (int nf = 0; nf < 4; nf++) {
                int rn = wn*32 + nf*8 + g;
                b[nf][0] = Vs[cur][rn][k8+t];    b[nf][1] = Vs[cur][rn][k8+t+4];
            }
            #pragma unroll
            for (int nf = 0; nf < 4; nf++)
                mma8(c[nf], a, b[nf]);
        }
        if (kn < kmax) {
            int nxt = cur ^ 1;
            #pragma unroll
            for (int u = 0; u < 2; u++) {
                *(uint4*)&Ps[nxt][lr][lc + u*4] = pv[u];
                *(uint4*)&Vs[nxt][lr][lc + u*4] = vv[u];
                l2acc += __uint_as_float(pv[u].x) + __uint_as_float(pv[u].y)
                       + __uint_as_float(pv[u].z) + __uint_as_float(pv[u].w);
            }
            __syncthreads();
        }
    }

    sl2[lr*4 + (tid & 3)] = l2acc;
    __syncthreads();

    int b = bh >> 3, h = bh & 7;
    #pragma unroll
    for (int half = 0; half < 2; half++) {
        int sl = wm*16 + g + half*8;
        int s  = m0 + sl;
        float l2v = sl2[sl*4] + sl2[sl*4+1] + sl2[sl*4+2] + sl2[sl*4+3];
        float sc  = (s == 0) ? 0.f : 1.f / l2v;
        #pragma unroll
        for (int nf = 0; nf < 4; nf++) {
            int dk = wn*32 + nf*8 + t*2;
            *(float2*)(g_at + ((size_t)b * SS + s) * DD + h*64 + dk)
                = make_float2(c[nf][half*2+0] * sc, c[nf][half*2+1] * sc);
        }
    }
}

// ---------------- launcher ----------------------------------------------------
extern "C" void kernel_launch(void* const* d_in, const int* in_sizes, int n_in,
                              void* d_out, int out_size)
{
    const float* q      = (const float*)d_in[0];
    const float* k      = (const float*)d_in[1];
    const float* v      = (const float*)d_in[2];
    const float* Wq     = (const float*)d_in[5];
    const float* bq     = (const float*)d_in[6];
    const float* Wk     = (const float*)d_in[7];
    const float* bk     = (const float*)d_in[8];
    const float* Wv     = (const float*)d_in[9];
    const float* bv     = (const float*)d_in[10];
    const float* Wo     = (const float*)d_in[11];
    const float* bo     = (const float*)d_in[12];
    const float* gammas = (const float*)d_in[13];
    float* out = (float*)d_out;

    cudaFuncSetAttribute(proj_kernel,
                         cudaFuncAttributeMaxDynamicSharedMemorySize, GEMM_SMEM_BYTES);
    cudaFuncSetAttribute(out_proj_kernel,
                         cudaFuncAttributeMaxDynamicSharedMemorySize, GEMM_SMEM_BYTES);
    cudaFuncSetAttribute(score_kernel,
                         cudaFuncAttributeMaxDynamicSharedMemorySize, GEMM_SMEM_BYTES);

    rope_tab_kernel<<<(SS * 32 + 255) / 256, 256>>>();
    proj_kernel<<<dim3(4, 32, 3), 256, GEMM_SMEM_BYTES>>>(q, k, v, Wq, bq, Wk, bk, Wv, bv);
    score_kernel<<<dim3(16, 16, 16), 256, GEMM_SMEM_BYTES>>>();
    row_kernel<<<BHH * SS, 256>>>(gammas);
    pv_kernel<<<dim3(32, 16), 256>>>();
    out_proj_kernel<<<dim3(4, 32), 256, GEMM_SMEM_BYTES>>>(Wo, bo, out);
}